// round 2
// baseline (speedup 1.0000x reference)
#include <cuda_runtime.h>
#include <math.h>

#define N_NODES 346
#define L_SEQ   50
#define D_EMB   300
#define H_HID   300
#define G4      1200   // 4*H

// ---------------------------------------------------------------------------
// Scratch pool (static device allocation — no cudaMalloc anywhere)
// ---------------------------------------------------------------------------
constexpr size_t A256(size_t x) { return (x + 255) & ~(size_t)255; }

constexpr size_t SZ_X   = (size_t)L_SEQ * N_NODES * D_EMB;   // 5,190,000
constexpr size_t SZ_P   = (size_t)L_SEQ * N_NODES * G4;      // 20,760,000
constexpr size_t SZ_O0  = (size_t)L_SEQ * N_NODES * 600;     // 10,380,000
constexpr size_t SZ_NG4 = (size_t)N_NODES * G4;              // 415,200
constexpr size_t SZ_NH  = (size_t)N_NODES * H_HID;           // 103,800

constexpr size_t OFF_X    = 0;
constexpr size_t OFF_P0F  = A256(OFF_X   + SZ_X);   // reused for P1F
constexpr size_t OFF_P0B  = A256(OFF_P0F + SZ_P);   // reused for P1B
constexpr size_t OFF_O0   = A256(OFF_P0B + SZ_P);
constexpr size_t OFF_G    = A256(OFF_O0  + SZ_O0);          // 2*N*G4
constexpr size_t OFF_HS0  = A256(OFF_G   + 2 * SZ_NG4);
constexpr size_t OFF_C4   = A256(OFF_HS0 + SZ_NG4);         // 4*N*H
constexpr size_t OFF_CAT  = A256(OFF_C4  + 4 * SZ_NH);      // N*2400
constexpr size_t OFF_WH   = A256(OFF_CAT + (size_t)N_NODES * 2400);
constexpr size_t OFF_ATT  = A256(OFF_WH  + SZ_NG4);         // N*N
constexpr size_t OFF_HS1  = A256(OFF_ATT + (size_t)N_NODES * N_NODES);
constexpr size_t OFF_HS2  = A256(OFF_HS1 + SZ_NG4);
constexpr size_t OFF_Z    = A256(OFF_HS2 + SZ_NG4);         // N*4800
constexpr size_t OFF_HC3  = A256(OFF_Z   + (size_t)N_NODES * 4800);  // N*9600
constexpr size_t OFF_U    = A256(OFF_HC3 + (size_t)N_NODES * 9600);
constexpr size_t OFF_V    = A256(OFF_U   + 512);
constexpr size_t OFF_S    = A256(OFF_V   + 32);
constexpr size_t OFF_E1   = A256(OFF_S   + 1280);
constexpr size_t OFF_E2   = A256(OFF_E1  + 512);
constexpr size_t OFF_BATT = A256(OFF_E2  + 512);
constexpr size_t OFF_EA   = A256(OFF_BATT + 512);
constexpr size_t POOL_SZ  = A256(OFF_EA + 2560);

__device__ float g_pool[POOL_SZ];

__device__ __forceinline__ float sigm_(float x) { return 1.0f / (1.0f + expf(-x)); }

// ---------------------------------------------------------------------------
// Tiled fp32 GEMM: C = epi(A @ op(B) + D)
//   TB=1 : C[m][n] = sum_k A[m*lda+k] * B[n*ldb+k]   (B row-major N x K, "@ W.T")
//   TB=0 : C[m][n] = sum_k A[m*lda+k] * B[k*ldb+n]   (B row-major K x N, "@ W")
//   D: null | bias row (ldd==0) | full matrix (ldd>0)
//   EPI: 0 none, 1 tanh, 2 elu
// ---------------------------------------------------------------------------
#define BM 64
#define BN 64
#define BK 16
#define SPAD 68

template<int TB, int EPI>
__device__ __forceinline__ void gemm_body(
    int M, int N, int K,
    const float* __restrict__ A, int lda,
    const float* __restrict__ B, int ldb,
    const float* __restrict__ Dm, int ldd,
    float* __restrict__ C, int ldc,
    float* As, float* Bs)
{
    const int m0 = blockIdx.y * BM;
    const int n0 = blockIdx.x * BN;
    const int tid = threadIdx.x;
    const int tx = tid & 15, ty = tid >> 4;

    float acc[4][4];
#pragma unroll
    for (int i = 0; i < 4; i++)
#pragma unroll
        for (int j = 0; j < 4; j++) acc[i][j] = 0.0f;

    for (int k0 = 0; k0 < K; k0 += BK) {
#pragma unroll
        for (int i = 0; i < 4; i++) {
            int idx = tid + i * 256;
            int m = idx >> 4, k = idx & 15;
            int gm = m0 + m, gk = k0 + k;
            As[k * SPAD + m] = (gm < M && gk < K) ? __ldg(&A[(size_t)gm * lda + gk]) : 0.0f;
        }
        if (TB) {
#pragma unroll
            for (int i = 0; i < 4; i++) {
                int idx = tid + i * 256;
                int j = idx >> 4, k = idx & 15;
                int gj = n0 + j, gk = k0 + k;
                Bs[k * SPAD + j] = (gj < N && gk < K) ? __ldg(&B[(size_t)gj * ldb + gk]) : 0.0f;
            }
        } else {
#pragma unroll
            for (int i = 0; i < 4; i++) {
                int idx = tid + i * 256;
                int j = idx & 63, k = idx >> 6;
                int gj = n0 + j, gk = k0 + k;
                Bs[k * SPAD + j] = (gj < N && gk < K) ? __ldg(&B[(size_t)gk * ldb + gj]) : 0.0f;
            }
        }
        __syncthreads();
#pragma unroll
        for (int kk = 0; kk < BK; kk++) {
            float4 av = *reinterpret_cast<const float4*>(&As[kk * SPAD + ty * 4]);
            float4 bv = *reinterpret_cast<const float4*>(&Bs[kk * SPAD + tx * 4]);
            float a[4] = {av.x, av.y, av.z, av.w};
            float b[4] = {bv.x, bv.y, bv.z, bv.w};
#pragma unroll
            for (int i = 0; i < 4; i++)
#pragma unroll
                for (int j = 0; j < 4; j++)
                    acc[i][j] += a[i] * b[j];
        }
        __syncthreads();
    }

#pragma unroll
    for (int i = 0; i < 4; i++) {
        int gm = m0 + ty * 4 + i;
        if (gm >= M) continue;
#pragma unroll
        for (int j = 0; j < 4; j++) {
            int gn = n0 + tx * 4 + j;
            if (gn >= N) continue;
            float v = acc[i][j];
            if (Dm) v += (ldd == 0) ? Dm[gn] : Dm[(size_t)gm * ldd + gn];
            if (EPI == 1) v = tanhf(v);
            if (EPI == 2) v = (v > 0.0f) ? v : expm1f(v);
            C[(size_t)gm * ldc + gn] = v;
        }
    }
}

template<int TB, int EPI>
__global__ void __launch_bounds__(256) gemm_kernel(
    int M, int N, int K,
    const float* __restrict__ A, int lda,
    const float* __restrict__ B, int ldb,
    const float* __restrict__ Dm, int ldd,
    float* __restrict__ C, int ldc)
{
    __shared__ float As[BK * SPAD], Bs[BK * SPAD];
    gemm_body<TB, EPI>(M, N, K, A, lda, B, ldb, Dm, ldd, C, ldc, As, Bs);
}

// Fused fwd+bwd recurrent GEMM for one LSTM step: z=0 fwd, z=1 bwd.
__global__ void __launch_bounds__(256) lstm_gemm_kernel(
    const float* __restrict__ hs, int colA0, int colA1,
    const float* __restrict__ B0, const float* __restrict__ B1,
    const float* __restrict__ D0, const float* __restrict__ D1,
    float* __restrict__ G)
{
    __shared__ float As[BK * SPAD], Bs[BK * SPAD];
    int z = blockIdx.z;
    const float* A  = hs + (z ? colA1 : colA0);
    const float* B  = z ? B1 : B0;
    const float* Dm = z ? D1 : D0;
    float* C = G + (size_t)z * N_NODES * G4;
    gemm_body<1, 0>(N_NODES, G4, H_HID, A, G4, B, H_HID, Dm, G4, C, G4, As, Bs);
}

// LSTM pointwise gate update; writes h into hs-concat layout (stride G4),
// and optionally the per-timestep output buffer o0 (stride 600).
__global__ void lstm_point_kernel(
    const float* __restrict__ G,
    float* __restrict__ hs, int hcol_f, int hcol_b,
    float* __restrict__ cbuf,      // c_f at +0, c_b at +N*H
    float* __restrict__ outbuf, int t)
{
    int idx = blockIdx.x * blockDim.x + threadIdx.x;
    const int total = 2 * N_NODES * H_HID;
    if (idx >= total) return;
    int dir = idx / (N_NODES * H_HID);
    int r = idx % (N_NODES * H_HID);
    int n = r / H_HID, j = r % H_HID;
    const float* g = G + (size_t)dir * N_NODES * G4 + (size_t)n * G4;
    float gi = g[j], gf = g[H_HID + j], gg = g[2 * H_HID + j], go = g[3 * H_HID + j];
    float* c = cbuf + (size_t)dir * N_NODES * H_HID;
    float cp = c[(size_t)n * H_HID + j];
    float cn = sigm_(gf) * cp + sigm_(gi) * tanhf(gg);
    float h = sigm_(go) * tanhf(cn);
    c[(size_t)n * H_HID + j] = cn;
    int hcol = dir ? hcol_b : hcol_f;
    hs[(size_t)n * G4 + hcol + j] = h;
    if (outbuf) {
        int tt = dir ? (L_SEQ - 1 - t) : t;
        outbuf[(size_t)tt * N_NODES * 600 + (size_t)n * 600 + dir * H_HID + j] = h;
    }
}

__global__ void memzero_kernel(float* p, int n)
{
    int i = blockIdx.x * blockDim.x + threadIdx.x;
    if (i < n) p[i] = 0.0f;
}

__global__ void embed_kernel(const int* __restrict__ tok,
                             const float* __restrict__ emb,
                             float* __restrict__ x)
{
    size_t idx = (size_t)blockIdx.x * blockDim.x + threadIdx.x;
    const size_t total = (size_t)L_SEQ * N_NODES * D_EMB;
    if (idx >= total) return;
    int d = (int)(idx % D_EMB);
    size_t r = idx / D_EMB;
    int n = (int)(r % N_NODES);
    int t = (int)(r / N_NODES);
    int tv = tok[n * L_SEQ + t];
    x[idx] = emb[(size_t)tv * D_EMB + d];
}

// out[row] = epi( dot(A[row,:K], w) )
template<int EPI>
__global__ void rows_dot_kernel(const float* __restrict__ A, int lda,
                                const float* __restrict__ w, int K,
                                float* __restrict__ out)
{
    __shared__ float red[8];
    const float* a = A + (size_t)blockIdx.x * lda;
    float s = 0.0f;
    for (int k = threadIdx.x; k < K; k += blockDim.x) s += a[k] * w[k];
#pragma unroll
    for (int o = 16; o > 0; o >>= 1) s += __shfl_down_sync(0xffffffffu, s, o);
    if ((threadIdx.x & 31) == 0) red[threadIdx.x >> 5] = s;
    __syncthreads();
    if (threadIdx.x == 0) {
        float t = 0.0f;
        int nw = blockDim.x >> 5;
        for (int i = 0; i < nw; i++) t += red[i];
        if (EPI == 1) t = tanhf(t);
        out[blockIdx.x] = t;
    }
}

// out[j] = scale * sum_n (w ? w[n] : 1) * A[n*lda + j]
__global__ void colsum_kernel(const float* __restrict__ A, int lda, int rows,
                              const float* __restrict__ w, float scale,
                              float* __restrict__ out, int ncols)
{
    int j = blockIdx.x * blockDim.x + threadIdx.x;
    if (j >= ncols) return;
    float s = 0.0f;
#pragma unroll 4
    for (int n = 0; n < rows; n++) {
        float v = A[(size_t)n * lda + j];
        s += w ? w[n] * v : v;
    }
    out[j] = s * scale;
}

// cat[n] = [ h[n] , gate(h)[n] ]
__global__ void gate_cat_kernel(const float* __restrict__ h,
                                const float* __restrict__ u,
                                const float* __restrict__ vsc,
                                const float* __restrict__ s,
                                float* __restrict__ cat)
{
    int idx = blockIdx.x * blockDim.x + threadIdx.x;
    if (idx >= N_NODES * G4) return;
    int n = idx / G4, j = idx % G4;
    float hv = h[(size_t)n * G4 + j];
    float h0 = h[j];
    float val;
    if (n == 0) {
        val = h0;
    } else {
        float g = sigm_(u[n] + vsc[0]);
        val = g * s[j] + (1.0f - g) * ((float)(N_NODES - 1) * h0);
    }
    cat[(size_t)n * 2400 + j] = hv;
    cat[(size_t)n * 2400 + 1200 + j] = val;
}

__global__ void att_softmax_kernel(const float* __restrict__ e1,
                                   const float* __restrict__ e2,
                                   const int* __restrict__ adj,
                                   float* __restrict__ att)
{
    __shared__ float warpred[4];
    __shared__ float s_max, s_sum;
    int i = blockIdx.x;
    float ei = e1[i];

    float mx = -3.4e38f;
    for (int j = threadIdx.x; j < N_NODES; j += blockDim.x) {
        float v = ei + e2[j];
        v = (v > 0.0f) ? v : 0.01f * v;
        if (adj[(size_t)i * N_NODES + j] <= 0) v = -9.0e15f;
        mx = fmaxf(mx, v);
    }
#pragma unroll
    for (int o = 16; o > 0; o >>= 1) mx = fmaxf(mx, __shfl_down_sync(0xffffffffu, mx, o));
    if ((threadIdx.x & 31) == 0) warpred[threadIdx.x >> 5] = mx;
    __syncthreads();
    if (threadIdx.x == 0) {
        float m2 = warpred[0];
        int nw = blockDim.x >> 5;
        for (int k = 1; k < nw; k++) m2 = fmaxf(m2, warpred[k]);
        s_max = m2;
    }
    __syncthreads();
    float smax = s_max;

    float sum = 0.0f;
    for (int j = threadIdx.x; j < N_NODES; j += blockDim.x) {
        float v = ei + e2[j];
        v = (v > 0.0f) ? v : 0.01f * v;
        if (adj[(size_t)i * N_NODES + j] <= 0) v = -9.0e15f;
        sum += expf(v - smax);
    }
#pragma unroll
    for (int o = 16; o > 0; o >>= 1) sum += __shfl_down_sync(0xffffffffu, sum, o);
    if ((threadIdx.x & 31) == 0) warpred[threadIdx.x >> 5] = sum;
    __syncthreads();
    if (threadIdx.x == 0) {
        float t = 0.0f;
        int nw = blockDim.x >> 5;
        for (int k = 0; k < nw; k++) t += warpred[k];
        s_sum = t;
    }
    __syncthreads();
    float inv = 1.0f / s_sum;

    for (int j = threadIdx.x; j < N_NODES; j += blockDim.x) {
        float v = ei + e2[j];
        v = (v > 0.0f) ? v : 0.01f * v;
        if (adj[(size_t)i * N_NODES + j] <= 0) v = -9.0e15f;
        att[(size_t)i * N_NODES + j] = expf(v - smax) * inv;
    }
}

// Z[n] = [hc, hs2[n], hc*hs2[n], hc - hs2[n]],  hc = hs2[0]
__global__ void zassemble_kernel(const float* __restrict__ h2, float* __restrict__ Z)
{
    int idx = blockIdx.x * blockDim.x + threadIdx.x;
    if (idx >= N_NODES * G4) return;
    int n = idx / G4, j = idx % G4;
    float a = h2[j];
    float b = h2[(size_t)n * G4 + j];
    size_t base = (size_t)n * 4800;
    Z[base + j]        = a;
    Z[base + 1200 + j] = b;
    Z[base + 2400 + j] = a * b;
    Z[base + 3600 + j] = a - b;
}

__global__ void final_kernel(const float* __restrict__ ea,
                             const float* __restrict__ Wlin,
                             const float* __restrict__ blin,
                             float* __restrict__ out)
{
    __shared__ float r0[8], r1[8];
    float s0 = 0.0f, s1 = 0.0f;
    for (int j = threadIdx.x; j < 2400; j += blockDim.x) {
        float e = ea[j];
        s0 += e * Wlin[j];
        s1 += e * Wlin[2400 + j];
    }
#pragma unroll
    for (int o = 16; o > 0; o >>= 1) {
        s0 += __shfl_down_sync(0xffffffffu, s0, o);
        s1 += __shfl_down_sync(0xffffffffu, s1, o);
    }
    if ((threadIdx.x & 31) == 0) { r0[threadIdx.x >> 5] = s0; r1[threadIdx.x >> 5] = s1; }
    __syncthreads();
    if (threadIdx.x == 0) {
        float l0 = 0.0f, l1 = 0.0f;
        int nw = blockDim.x >> 5;
        for (int i = 0; i < nw; i++) { l0 += r0[i]; l1 += r1[i]; }
        l0 += blin[0]; l1 += blin[1];
        float m = fmaxf(l0, l1);
        float e0 = expf(l0 - m), e1v = expf(l1 - m);
        float inv = 1.0f / (e0 + e1v);
        out[0] = e0 * inv;
        out[1] = e1v * inv;
    }
}

// ---------------------------------------------------------------------------
// Host orchestration
// ---------------------------------------------------------------------------
static inline dim3 gemm_grid(int M, int N) {
    return dim3((N + BN - 1) / BN, (M + BM - 1) / BM);
}

static void run_gate_gat(const float* h_in, float* h_out,
                         const float* gate_W, const float* gate_U,
                         const float* W_gat, const float* a_gat,
                         const int* adj, float* pool)
{
    float* U   = pool + OFF_U;
    float* Vb  = pool + OFF_V;
    float* S   = pool + OFF_S;
    float* CAT = pool + OFF_CAT;
    float* WHp = pool + OFF_WH;
    float* E1  = pool + OFF_E1;
    float* E2  = pool + OFF_E2;
    float* ATT = pool + OFF_ATT;

    // _gate
    rows_dot_kernel<0><<<N_NODES, 256>>>(h_in, G4, gate_W, G4, U);
    rows_dot_kernel<0><<<1, 256>>>(h_in, G4, gate_U, G4, Vb);
    colsum_kernel<<<(G4 + 255) / 256, 256>>>(h_in + G4, G4, N_NODES - 1, nullptr, 1.0f, S, G4);
    gate_cat_kernel<<<(N_NODES * G4 + 255) / 256, 256>>>(h_in, U, Vb, S, CAT);

    // _gat
    gemm_kernel<0, 0><<<gemm_grid(N_NODES, G4), 256>>>(
        N_NODES, G4, 2400, CAT, 2400, W_gat, G4, nullptr, 0, WHp, G4);
    rows_dot_kernel<0><<<N_NODES, 256>>>(WHp, G4, a_gat, G4, E1);
    rows_dot_kernel<0><<<N_NODES, 256>>>(WHp, G4, a_gat + G4, G4, E2);
    att_softmax_kernel<<<N_NODES, 128>>>(E1, E2, adj, ATT);
    gemm_kernel<0, 2><<<gemm_grid(N_NODES, G4), 256>>>(
        N_NODES, G4, N_NODES, ATT, N_NODES, WHp, G4, nullptr, 0, h_out, G4);
}

extern "C" void kernel_launch(void* const* d_in, const int* in_sizes, int n_in,
                              void* d_out, int out_size)
{
    (void)in_sizes; (void)n_in; (void)out_size;

    float* pool = nullptr;
    cudaGetSymbolAddress((void**)&pool, g_pool);

    const int*   tokens  = (const int*)d_in[0];
    const int*   adj     = (const int*)d_in[1];
    const float* emb     = (const float*)d_in[2];
    const float* Wih_l0f = (const float*)d_in[3];
    const float* Whh_l0f = (const float*)d_in[4];
    const float* b_l0f   = (const float*)d_in[5];
    const float* Wih_l0b = (const float*)d_in[6];
    const float* Whh_l0b = (const float*)d_in[7];
    const float* b_l0b   = (const float*)d_in[8];
    const float* Wih_l1f = (const float*)d_in[9];
    const float* Whh_l1f = (const float*)d_in[10];
    const float* b_l1f   = (const float*)d_in[11];
    const float* Wih_l1b = (const float*)d_in[12];
    const float* Whh_l1b = (const float*)d_in[13];
    const float* b_l1b   = (const float*)d_in[14];
    const float* W_gat   = (const float*)d_in[15];
    const float* a_gat   = (const float*)d_in[16];
    const float* gate_W  = (const float*)d_in[17];
    const float* gate_U  = (const float*)d_in[18];
    const float* FC1     = (const float*)d_in[19];
    const float* FC2     = (const float*)d_in[20];
    const float* Wlin    = (const float*)d_in[21];
    const float* blin    = (const float*)d_in[22];
    float* out = (float*)d_out;

    float* X   = pool + OFF_X;
    float* P0F = pool + OFF_P0F;   // also P1F
    float* P0B = pool + OFF_P0B;   // also P1B
    float* O0  = pool + OFF_O0;
    float* G   = pool + OFF_G;
    float* HS0 = pool + OFF_HS0;
    float* C4  = pool + OFF_C4;
    float* HS1 = pool + OFF_HS1;
    float* HS2 = pool + OFF_HS2;
    float* Z   = pool + OFF_Z;
    float* HC3 = pool + OFF_HC3;
    float* BATT = pool + OFF_BATT;
    float* EA  = pool + OFF_EA;

    const int LN = L_SEQ * N_NODES;   // 17300

    // init states (h in HS0 layout, c in C4)
    memzero_kernel<<<((int)SZ_NG4 + 255) / 256, 256>>>(HS0, (int)SZ_NG4);
    memzero_kernel<<<(4 * (int)SZ_NH + 255) / 256, 256>>>(C4, 4 * (int)SZ_NH);

    // embedding: x[t][n][d] = emb[tokens[n][t]][d]
    embed_kernel<<<(int)((SZ_X + 255) / 256), 256>>>(tokens, emb, X);

    // layer-0 input projections (all timesteps at once)
    gemm_kernel<1, 0><<<gemm_grid(LN, G4), 256>>>(
        LN, G4, D_EMB, X, D_EMB, Wih_l0f, D_EMB, b_l0f, 0, P0F, G4);
    gemm_kernel<1, 0><<<gemm_grid(LN, G4), 256>>>(
        LN, G4, D_EMB, X, D_EMB, Wih_l0b, D_EMB, b_l0b, 0, P0B, G4);

    // layer-0 scans (fwd+bwd fused per step)
    {
        dim3 grid = gemm_grid(N_NODES, G4); grid.z = 2;
        int ptblocks = (2 * N_NODES * H_HID + 255) / 256;
        for (int t = 0; t < L_SEQ; t++) {
            lstm_gemm_kernel<<<grid, 256>>>(
                HS0, 0, 300, Whh_l0f, Whh_l0b,
                P0F + (size_t)t * N_NODES * G4,
                P0B + (size_t)(L_SEQ - 1 - t) * N_NODES * G4, G);
            lstm_point_kernel<<<ptblocks, 256>>>(G, HS0, 0, 300, C4, O0, t);
        }
    }

    // layer-1 input projections (reuse P0F/P0B storage)
    gemm_kernel<1, 0><<<gemm_grid(LN, G4), 256>>>(
        LN, G4, 600, O0, 600, Wih_l1f, 600, b_l1f, 0, P0F, G4);
    gemm_kernel<1, 0><<<gemm_grid(LN, G4), 256>>>(
        LN, G4, 600, O0, 600, Wih_l1b, 600, b_l1b, 0, P0B, G4);

    // layer-1 scans (states in HS0 cols 600/900, c in C4 slices 2,3; no outputs)
    {
        dim3 grid = gemm_grid(N_NODES, G4); grid.z = 2;
        int ptblocks = (2 * N_NODES * H_HID + 255) / 256;
        for (int t = 0; t < L_SEQ; t++) {
            lstm_gemm_kernel<<<grid, 256>>>(
                HS0, 600, 900, Whh_l1f, Whh_l1b,
                P0F + (size_t)t * N_NODES * G4,
                P0B + (size_t)(L_SEQ - 1 - t) * N_NODES * G4, G);
            lstm_point_kernel<<<ptblocks, 256>>>(G, HS0, 600, 900, C4 + 2 * SZ_NH, nullptr, t);
        }
    }

    // HS0 now holds [hf0|hb0|hf1|hb1] per row -> two gate+GAT stages
    run_gate_gat(HS0, HS1, gate_W, gate_U, W_gat, a_gat, adj, pool);
    run_gate_gat(HS1, HS2, gate_W, gate_U, W_gat, a_gat, adj, pool);

    // final head
    zassemble_kernel<<<(N_NODES * G4 + 255) / 256, 256>>>(HS2, Z);
    gemm_kernel<0, 1><<<gemm_grid(N_NODES, 9600), 256>>>(
        N_NODES, 9600, 4800, Z, 4800, FC1, 9600, nullptr, 0, HC3, 9600);
    rows_dot_kernel<1><<<N_NODES, 256>>>(HC3, 9600, FC2, 9600, BATT);
    colsum_kernel<<<(G4 + 255) / 256, 256>>>(HS2, G4, N_NODES, nullptr,
                                             1.0f / (float)N_NODES, EA, G4);
    colsum_kernel<<<(G4 + 255) / 256, 256>>>(HS2, G4, N_NODES, BATT, 1.0f, EA + G4, G4);
    final_kernel<<<1, 256>>>(EA, Wlin, blin, out);
}

// round 3
// speedup vs baseline: 1.0209x; 1.0209x over previous
#include <cuda_runtime.h>
#include <math.h>

#define N_NODES 346
#define L_SEQ   50
#define D_EMB   300
#define H_HID   300
#define G4      1200   // 4*H

// ---------------------------------------------------------------------------
// Scratch pool (static device allocation — no cudaMalloc anywhere)
// ---------------------------------------------------------------------------
constexpr size_t A256(size_t x) { return (x + 255) & ~(size_t)255; }

constexpr size_t SZ_X   = (size_t)L_SEQ * N_NODES * D_EMB;   // 5,190,000
constexpr size_t SZ_P   = (size_t)L_SEQ * N_NODES * G4;      // 20,760,000
constexpr size_t SZ_O0  = (size_t)L_SEQ * N_NODES * 600;     // 10,380,000
constexpr size_t SZ_NG4 = (size_t)N_NODES * G4;              // 415,200
constexpr size_t SZ_NH  = (size_t)N_NODES * H_HID;           // 103,800

constexpr size_t OFF_X    = 0;
constexpr size_t OFF_P0F  = A256(OFF_X   + SZ_X);   // reused for P1F
constexpr size_t OFF_P0B  = A256(OFF_P0F + SZ_P);   // reused for P1B
constexpr size_t OFF_O0   = A256(OFF_P0B + SZ_P);
constexpr size_t OFF_HSA  = A256(OFF_O0  + SZ_O0);
constexpr size_t OFF_HSB  = A256(OFF_HSA + SZ_NG4);
constexpr size_t OFF_C4   = A256(OFF_HSB + SZ_NG4);         // 4*N*H
constexpr size_t OFF_CAT  = A256(OFF_C4  + 4 * SZ_NH);      // N*2400
constexpr size_t OFF_WH   = A256(OFF_CAT + (size_t)N_NODES * 2400);
constexpr size_t OFF_ATT  = A256(OFF_WH  + SZ_NG4);         // N*N
constexpr size_t OFF_HS1  = A256(OFF_ATT + (size_t)N_NODES * N_NODES);
constexpr size_t OFF_HS2  = A256(OFF_HS1 + SZ_NG4);
constexpr size_t OFF_Z    = A256(OFF_HS2 + SZ_NG4);         // N*4800
constexpr size_t OFF_HC3  = A256(OFF_Z   + (size_t)N_NODES * 4800);  // N*9600
// reordered LSTM weights (row r = j*4 + gate)
constexpr size_t OFF_WHHR  = A256(OFF_HC3  + (size_t)N_NODES * 9600); // 4 x 1200*300
constexpr size_t OFF_WIHR0 = A256(OFF_WHHR + 4 * (size_t)G4 * H_HID); // 2 x 1200*300
constexpr size_t OFF_WIHR1 = A256(OFF_WIHR0 + 2 * (size_t)G4 * 300);  // 2 x 1200*600
constexpr size_t OFF_BR    = A256(OFF_WIHR1 + 2 * (size_t)G4 * 600);  // 4 x 1200
constexpr size_t OFF_U    = A256(OFF_BR  + 4 * (size_t)G4);
constexpr size_t OFF_V    = A256(OFF_U   + 512);
constexpr size_t OFF_S    = A256(OFF_V   + 32);
constexpr size_t OFF_E1   = A256(OFF_S   + 1280);
constexpr size_t OFF_E2   = A256(OFF_E1  + 512);
constexpr size_t OFF_BATT = A256(OFF_E2  + 512);
constexpr size_t OFF_EA   = A256(OFF_BATT + 512);
constexpr size_t POOL_SZ  = A256(OFF_EA + 2560);

__device__ float g_pool[POOL_SZ];

__device__ __forceinline__ float sigm_(float x) { return 1.0f / (1.0f + expf(-x)); }

// ---------------------------------------------------------------------------
// 64x64x16 GEMM accumulator core (4x4 per thread), shared by small GEMM and
// the fused LSTM step kernel.
//   TB=1 : C[m][n] = sum_k A[m*lda+k] * B[n*ldb+k]
//   TB=0 : C[m][n] = sum_k A[m*lda+k] * B[k*ldb+n]
// ---------------------------------------------------------------------------
#define BM 64
#define BN 64
#define BK 16
#define SPAD 68

template<int TB>
__device__ __forceinline__ void gemm_acc64(
    int M, int N, int K,
    const float* __restrict__ A, int lda,
    const float* __restrict__ B, int ldb,
    float* As, float* Bs, float acc[4][4],
    int m0, int n0, int tid, int tx, int ty)
{
#pragma unroll
    for (int i = 0; i < 4; i++)
#pragma unroll
        for (int j = 0; j < 4; j++) acc[i][j] = 0.0f;

    for (int k0 = 0; k0 < K; k0 += BK) {
#pragma unroll
        for (int i = 0; i < 4; i++) {
            int idx = tid + i * 256;
            int m = idx >> 4, k = idx & 15;
            int gm = m0 + m, gk = k0 + k;
            As[k * SPAD + m] = (gm < M && gk < K) ? __ldg(&A[(size_t)gm * lda + gk]) : 0.0f;
        }
        if (TB) {
#pragma unroll
            for (int i = 0; i < 4; i++) {
                int idx = tid + i * 256;
                int j = idx >> 4, k = idx & 15;
                int gj = n0 + j, gk = k0 + k;
                Bs[k * SPAD + j] = (gj < N && gk < K) ? __ldg(&B[(size_t)gj * ldb + gk]) : 0.0f;
            }
        } else {
#pragma unroll
            for (int i = 0; i < 4; i++) {
                int idx = tid + i * 256;
                int j = idx & 63, k = idx >> 6;
                int gj = n0 + j, gk = k0 + k;
                Bs[k * SPAD + j] = (gj < N && gk < K) ? __ldg(&B[(size_t)gk * ldb + gj]) : 0.0f;
            }
        }
        __syncthreads();
#pragma unroll
        for (int kk = 0; kk < BK; kk++) {
            float4 av = *reinterpret_cast<const float4*>(&As[kk * SPAD + ty * 4]);
            float4 bv = *reinterpret_cast<const float4*>(&Bs[kk * SPAD + tx * 4]);
            float a[4] = {av.x, av.y, av.z, av.w};
            float b[4] = {bv.x, bv.y, bv.z, bv.w};
#pragma unroll
            for (int i = 0; i < 4; i++)
#pragma unroll
                for (int j = 0; j < 4; j++)
                    acc[i][j] += a[i] * b[j];
        }
        __syncthreads();
    }
}

// Generic 64x64 GEMM with epilogue: EPI 0 none, 1 tanh, 2 elu
template<int TB, int EPI>
__global__ void __launch_bounds__(256) gemm_kernel(
    int M, int N, int K,
    const float* __restrict__ A, int lda,
    const float* __restrict__ B, int ldb,
    const float* __restrict__ Dm, int ldd,
    float* __restrict__ C, int ldc)
{
    __shared__ float As[BK * SPAD], Bs[BK * SPAD];
    const int m0 = blockIdx.y * BM, n0 = blockIdx.x * BN;
    const int tid = threadIdx.x, tx = tid & 15, ty = tid >> 4;
    float acc[4][4];
    gemm_acc64<TB>(M, N, K, A, lda, B, ldb, As, Bs, acc, m0, n0, tid, tx, ty);

#pragma unroll
    for (int i = 0; i < 4; i++) {
        int gm = m0 + ty * 4 + i;
        if (gm >= M) continue;
#pragma unroll
        for (int j = 0; j < 4; j++) {
            int gn = n0 + tx * 4 + j;
            if (gn >= N) continue;
            float v = acc[i][j];
            if (Dm) v += (ldd == 0) ? Dm[gn] : Dm[(size_t)gm * ldd + gn];
            if (EPI == 1) v = tanhf(v);
            if (EPI == 2) v = (v > 0.0f) ? v : expm1f(v);
            C[(size_t)gm * ldc + gn] = v;
        }
    }
}

// ---------------------------------------------------------------------------
// 128x128x8 GEMM, 8x8 per thread — for the big-M / big-N GEMMs (L1-bound fix)
// ---------------------------------------------------------------------------
#define XBM 128
#define XBN 128
#define XBK 8
#define XPAD 132

template<int TB, int EPI>
__global__ void __launch_bounds__(256) gemm128_kernel(
    int M, int N, int K,
    const float* __restrict__ A, int lda,
    const float* __restrict__ B, int ldb,
    const float* __restrict__ Dm, int ldd,
    float* __restrict__ C, int ldc)
{
    __shared__ float As[XBK * XPAD], Bs[XBK * XPAD];
    const int m0 = blockIdx.y * XBM, n0 = blockIdx.x * XBN;
    const int tid = threadIdx.x, tx = tid & 15, ty = tid >> 4;

    float acc[8][8];
#pragma unroll
    for (int i = 0; i < 8; i++)
#pragma unroll
        for (int j = 0; j < 8; j++) acc[i][j] = 0.0f;

    for (int k0 = 0; k0 < K; k0 += XBK) {
#pragma unroll
        for (int l = 0; l < 4; l++) {
            int idx = tid + l * 256;
            int m = idx >> 3, k = idx & 7;
            int gm = m0 + m, gk = k0 + k;
            As[k * XPAD + m] = (gm < M && gk < K) ? __ldg(&A[(size_t)gm * lda + gk]) : 0.0f;
        }
        if (TB) {
#pragma unroll
            for (int l = 0; l < 4; l++) {
                int idx = tid + l * 256;
                int j = idx >> 3, k = idx & 7;
                int gj = n0 + j, gk = k0 + k;
                Bs[k * XPAD + j] = (gj < N && gk < K) ? __ldg(&B[(size_t)gj * ldb + gk]) : 0.0f;
            }
        } else {
#pragma unroll
            for (int l = 0; l < 4; l++) {
                int idx = tid + l * 256;
                int k = idx >> 7, j = idx & 127;
                int gj = n0 + j, gk = k0 + k;
                Bs[k * XPAD + j] = (gj < N && gk < K) ? __ldg(&B[(size_t)gk * ldb + gj]) : 0.0f;
            }
        }
        __syncthreads();
#pragma unroll
        for (int kk = 0; kk < XBK; kk++) {
            float a[8], b[8];
            float4 a0 = *reinterpret_cast<const float4*>(&As[kk * XPAD + ty * 8]);
            float4 a1 = *reinterpret_cast<const float4*>(&As[kk * XPAD + ty * 8 + 4]);
            float4 b0 = *reinterpret_cast<const float4*>(&Bs[kk * XPAD + tx * 8]);
            float4 b1 = *reinterpret_cast<const float4*>(&Bs[kk * XPAD + tx * 8 + 4]);
            a[0]=a0.x; a[1]=a0.y; a[2]=a0.z; a[3]=a0.w;
            a[4]=a1.x; a[5]=a1.y; a[6]=a1.z; a[7]=a1.w;
            b[0]=b0.x; b[1]=b0.y; b[2]=b0.z; b[3]=b0.w;
            b[4]=b1.x; b[5]=b1.y; b[6]=b1.z; b[7]=b1.w;
#pragma unroll
            for (int i = 0; i < 8; i++)
#pragma unroll
                for (int j = 0; j < 8; j++)
                    acc[i][j] += a[i] * b[j];
        }
        __syncthreads();
    }

#pragma unroll
    for (int i = 0; i < 8; i++) {
        int gm = m0 + ty * 8 + i;
        if (gm >= M) continue;
#pragma unroll
        for (int j = 0; j < 8; j++) {
            int gn = n0 + tx * 8 + j;
            if (gn >= N) continue;
            float v = acc[i][j];
            if (Dm) v += (ldd == 0) ? Dm[gn] : Dm[(size_t)gm * ldd + gn];
            if (EPI == 1) v = tanhf(v);
            if (EPI == 2) v = (v > 0.0f) ? v : expm1f(v);
            C[(size_t)gm * ldc + gn] = v;
        }
    }
}

// ---------------------------------------------------------------------------
// Fused LSTM step: G = h_in @ Whh_r.T + P_r  then cell update in epilogue.
// Weights/P are gate-interleaved (row r = j*4 + gate), so each thread's 4
// consecutive output columns are (i,f,g,o) of one hidden unit j.
// z=0 forward dir, z=1 backward dir.
// ---------------------------------------------------------------------------
__global__ void __launch_bounds__(256) lstm_fused_kernel(
    const float* __restrict__ hs_in, float* __restrict__ hs_out,
    int hcol_f, int hcol_b,
    const float* __restrict__ Whh_rf, const float* __restrict__ Whh_rb,
    const float* __restrict__ Pf, const float* __restrict__ Pb,
    float* __restrict__ cbuf,            // [2][N][H]
    float* __restrict__ outbuf, int t)   // o0 or null
{
    __shared__ float As[BK * SPAD], Bs[BK * SPAD];
    const int z = blockIdx.z;
    const int hcol = z ? hcol_b : hcol_f;
    const float* A = hs_in + hcol;
    const float* Bw = z ? Whh_rb : Whh_rf;
    const float* P  = z ? Pb : Pf;

    const int m0 = blockIdx.y * BM, n0 = blockIdx.x * BN;
    const int tid = threadIdx.x, tx = tid & 15, ty = tid >> 4;
    float acc[4][4];
    gemm_acc64<1>(N_NODES, G4, H_HID, A, G4, Bw, H_HID, As, Bs, acc, m0, n0, tid, tx, ty);

    const int r0 = n0 + tx * 4;
    if (r0 + 3 >= G4) return;
    const int j = r0 >> 2;
    float* c = cbuf + (size_t)z * N_NODES * H_HID;

#pragma unroll
    for (int i = 0; i < 4; i++) {
        int gm = m0 + ty * 4 + i;
        if (gm >= N_NODES) continue;
        const float* p = P + (size_t)gm * G4 + r0;
        float gi = acc[i][0] + p[0];
        float gf = acc[i][1] + p[1];
        float gg = acc[i][2] + p[2];
        float go = acc[i][3] + p[3];
        float cp = c[(size_t)gm * H_HID + j];
        float cn = sigm_(gf) * cp + sigm_(gi) * tanhf(gg);
        float h  = sigm_(go) * tanhf(cn);
        c[(size_t)gm * H_HID + j] = cn;
        hs_out[(size_t)gm * G4 + hcol + j] = h;
        if (outbuf) {
            int tt = z ? (L_SEQ - 1 - t) : t;
            outbuf[(size_t)tt * N_NODES * 600 + (size_t)gm * 600 + z * H_HID + j] = h;
        }
    }
}

// Reorder LSTM weight rows: out[j*4+g][k] = in[g*H + j][k]
__global__ void reorder_rows_kernel(const float* __restrict__ in,
                                    float* __restrict__ out, int K)
{
    size_t idx = (size_t)blockIdx.x * blockDim.x + threadIdx.x;
    if (idx >= (size_t)G4 * K) return;
    int r = (int)(idx / K), k = (int)(idx % K);
    int j = r >> 2, g = r & 3;
    out[(size_t)r * K + k] = in[(size_t)(g * H_HID + j) * K + k];
}

__global__ void memzero_kernel(float* p, int n)
{
    int i = blockIdx.x * blockDim.x + threadIdx.x;
    if (i < n) p[i] = 0.0f;
}

__global__ void embed_kernel(const int* __restrict__ tok,
                             const float* __restrict__ emb,
                             float* __restrict__ x)
{
    size_t idx = (size_t)blockIdx.x * blockDim.x + threadIdx.x;
    const size_t total = (size_t)L_SEQ * N_NODES * D_EMB;
    if (idx >= total) return;
    int d = (int)(idx % D_EMB);
    size_t r = idx / D_EMB;
    int n = (int)(r % N_NODES);
    int t = (int)(r / N_NODES);
    int tv = tok[n * L_SEQ + t];
    x[idx] = emb[(size_t)tv * D_EMB + d];
}

// out[row] = epi( dot(A[row,:K], w) )
template<int EPI>
__global__ void rows_dot_kernel(const float* __restrict__ A, int lda,
                                const float* __restrict__ w, int K,
                                float* __restrict__ out)
{
    __shared__ float red[8];
    const float* a = A + (size_t)blockIdx.x * lda;
    float s = 0.0f;
    for (int k = threadIdx.x; k < K; k += blockDim.x) s += a[k] * w[k];
#pragma unroll
    for (int o = 16; o > 0; o >>= 1) s += __shfl_down_sync(0xffffffffu, s, o);
    if ((threadIdx.x & 31) == 0) red[threadIdx.x >> 5] = s;
    __syncthreads();
    if (threadIdx.x == 0) {
        float t = 0.0f;
        int nw = blockDim.x >> 5;
        for (int i = 0; i < nw; i++) t += red[i];
        if (EPI == 1) t = tanhf(t);
        out[blockIdx.x] = t;
    }
}

// out[j] = scale * sum_n (w ? w[n] : 1) * A[n*lda + j]
__global__ void colsum_kernel(const float* __restrict__ A, int lda, int rows,
                              const float* __restrict__ w, float scale,
                              float* __restrict__ out, int ncols)
{
    int j = blockIdx.x * blockDim.x + threadIdx.x;
    if (j >= ncols) return;
    float s = 0.0f;
#pragma unroll 4
    for (int n = 0; n < rows; n++) {
        float v = A[(size_t)n * lda + j];
        s += w ? w[n] * v : v;
    }
    out[j] = s * scale;
}

// cat[n] = [ h[n] , gate(h)[n] ]
__global__ void gate_cat_kernel(const float* __restrict__ h,
                                const float* __restrict__ u,
                                const float* __restrict__ vsc,
                                const float* __restrict__ s,
                                float* __restrict__ cat)
{
    int idx = blockIdx.x * blockDim.x + threadIdx.x;
    if (idx >= N_NODES * G4) return;
    int n = idx / G4, j = idx % G4;
    float hv = h[(size_t)n * G4 + j];
    float h0 = h[j];
    float val;
    if (n == 0) {
        val = h0;
    } else {
        float g = sigm_(u[n] + vsc[0]);
        val = g * s[j] + (1.0f - g) * ((float)(N_NODES - 1) * h0);
    }
    cat[(size_t)n * 2400 + j] = hv;
    cat[(size_t)n * 2400 + 1200 + j] = val;
}

__global__ void att_softmax_kernel(const float* __restrict__ e1,
                                   const float* __restrict__ e2,
                                   const int* __restrict__ adj,
                                   float* __restrict__ att)
{
    __shared__ float warpred[4];
    __shared__ float s_max, s_sum;
    int i = blockIdx.x;
    float ei = e1[i];

    float mx = -3.4e38f;
    for (int j = threadIdx.x; j < N_NODES; j += blockDim.x) {
        float v = ei + e2[j];
        v = (v > 0.0f) ? v : 0.01f * v;
        if (adj[(size_t)i * N_NODES + j] <= 0) v = -9.0e15f;
        mx = fmaxf(mx, v);
    }
#pragma unroll
    for (int o = 16; o > 0; o >>= 1) mx = fmaxf(mx, __shfl_down_sync(0xffffffffu, mx, o));
    if ((threadIdx.x & 31) == 0) warpred[threadIdx.x >> 5] = mx;
    __syncthreads();
    if (threadIdx.x == 0) {
        float m2 = warpred[0];
        int nw = blockDim.x >> 5;
        for (int k = 1; k < nw; k++) m2 = fmaxf(m2, warpred[k]);
        s_max = m2;
    }
    __syncthreads();
    float smax = s_max;

    float sum = 0.0f;
    for (int j = threadIdx.x; j < N_NODES; j += blockDim.x) {
        float v = ei + e2[j];
        v = (v > 0.0f) ? v : 0.01f * v;
        if (adj[(size_t)i * N_NODES + j] <= 0) v = -9.0e15f;
        sum += expf(v - smax);
    }
#pragma unroll
    for (int o = 16; o > 0; o >>= 1) sum += __shfl_down_sync(0xffffffffu, sum, o);
    if ((threadIdx.x & 31) == 0) warpred[threadIdx.x >> 5] = sum;
    __syncthreads();
    if (threadIdx.x == 0) {
        float t = 0.0f;
        int nw = blockDim.x >> 5;
        for (int k = 0; k < nw; k++) t += warpred[k];
        s_sum = t;
    }
    __syncthreads();
    float inv = 1.0f / s_sum;

    for (int j = threadIdx.x; j < N_NODES; j += blockDim.x) {
        float v = ei + e2[j];
        v = (v > 0.0f) ? v : 0.01f * v;
        if (adj[(size_t)i * N_NODES + j] <= 0) v = -9.0e15f;
        att[(size_t)i * N_NODES + j] = expf(v - smax) * inv;
    }
}

// Z[n] = [hc, hs2[n], hc*hs2[n], hc - hs2[n]],  hc = hs2[0]
__global__ void zassemble_kernel(const float* __restrict__ h2, float* __restrict__ Z)
{
    int idx = blockIdx.x * blockDim.x + threadIdx.x;
    if (idx >= N_NODES * G4) return;
    int n = idx / G4, j = idx % G4;
    float a = h2[j];
    float b = h2[(size_t)n * G4 + j];
    size_t base = (size_t)n * 4800;
    Z[base + j]        = a;
    Z[base + 1200 + j] = b;
    Z[base + 2400 + j] = a * b;
    Z[base + 3600 + j] = a - b;
}

__global__ void final_kernel(const float* __restrict__ ea,
                             const float* __restrict__ Wlin,
                             const float* __restrict__ blin,
                             float* __restrict__ out)
{
    __shared__ float r0[8], r1[8];
    float s0 = 0.0f, s1 = 0.0f;
    for (int j = threadIdx.x; j < 2400; j += blockDim.x) {
        float e = ea[j];
        s0 += e * Wlin[j];
        s1 += e * Wlin[2400 + j];
    }
#pragma unroll
    for (int o = 16; o > 0; o >>= 1) {
        s0 += __shfl_down_sync(0xffffffffu, s0, o);
        s1 += __shfl_down_sync(0xffffffffu, s1, o);
    }
    if ((threadIdx.x & 31) == 0) { r0[threadIdx.x >> 5] = s0; r1[threadIdx.x >> 5] = s1; }
    __syncthreads();
    if (threadIdx.x == 0) {
        float l0 = 0.0f, l1 = 0.0f;
        int nw = blockDim.x >> 5;
        for (int i = 0; i < nw; i++) { l0 += r0[i]; l1 += r1[i]; }
        l0 += blin[0]; l1 += blin[1];
        float m = fmaxf(l0, l1);
        float e0 = expf(l0 - m), e1v = expf(l1 - m);
        float inv = 1.0f / (e0 + e1v);
        out[0] = e0 * inv;
        out[1] = e1v * inv;
    }
}

// ---------------------------------------------------------------------------
// Host orchestration
// ---------------------------------------------------------------------------
static inline dim3 grid64(int M, int N)  { return dim3((N + BN - 1) / BN, (M + BM - 1) / BM); }
static inline dim3 grid128(int M, int N) { return dim3((N + XBN - 1) / XBN, (M + XBM - 1) / XBM); }

static void run_gate_gat(const float* h_in, float* h_out,
                         const float* gate_W, const float* gate_U,
                         const float* W_gat, const float* a_gat,
                         const int* adj, float* pool)
{
    float* U   = pool + OFF_U;
    float* Vb  = pool + OFF_V;
    float* S   = pool + OFF_S;
    float* CAT = pool + OFF_CAT;
    float* WHp = pool + OFF_WH;
    float* E1  = pool + OFF_E1;
    float* E2  = pool + OFF_E2;
    float* ATT = pool + OFF_ATT;

    rows_dot_kernel<0><<<N_NODES, 256>>>(h_in, G4, gate_W, G4, U);
    rows_dot_kernel<0><<<1, 256>>>(h_in, G4, gate_U, G4, Vb);
    colsum_kernel<<<(G4 + 255) / 256, 256>>>(h_in + G4, G4, N_NODES - 1, nullptr, 1.0f, S, G4);
    gate_cat_kernel<<<(N_NODES * G4 + 255) / 256, 256>>>(h_in, U, Vb, S, CAT);

    gemm_kernel<0, 0><<<grid64(N_NODES, G4), 256>>>(
        N_NODES, G4, 2400, CAT, 2400, W_gat, G4, nullptr, 0, WHp, G4);
    rows_dot_kernel<0><<<N_NODES, 256>>>(WHp, G4, a_gat, G4, E1);
    rows_dot_kernel<0><<<N_NODES, 256>>>(WHp, G4, a_gat + G4, G4, E2);
    att_softmax_kernel<<<N_NODES, 128>>>(E1, E2, adj, ATT);
    gemm_kernel<0, 2><<<grid64(N_NODES, G4), 256>>>(
        N_NODES, G4, N_NODES, ATT, N_NODES, WHp, G4, nullptr, 0, h_out, G4);
}

extern "C" void kernel_launch(void* const* d_in, const int* in_sizes, int n_in,
                              void* d_out, int out_size)
{
    (void)in_sizes; (void)n_in; (void)out_size;

    float* pool = nullptr;
    cudaGetSymbolAddress((void**)&pool, g_pool);

    const int*   tokens  = (const int*)d_in[0];
    const int*   adj     = (const int*)d_in[1];
    const float* emb     = (const float*)d_in[2];
    const float* Wih_l0f = (const float*)d_in[3];
    const float* Whh_l0f = (const float*)d_in[4];
    const float* b_l0f   = (const float*)d_in[5];
    const float* Wih_l0b = (const float*)d_in[6];
    const float* Whh_l0b = (const float*)d_in[7];
    const float* b_l0b   = (const float*)d_in[8];
    const float* Wih_l1f = (const float*)d_in[9];
    const float* Whh_l1f = (const float*)d_in[10];
    const float* b_l1f   = (const float*)d_in[11];
    const float* Wih_l1b = (const float*)d_in[12];
    const float* Whh_l1b = (const float*)d_in[13];
    const float* b_l1b   = (const float*)d_in[14];
    const float* W_gat   = (const float*)d_in[15];
    const float* a_gat   = (const float*)d_in[16];
    const float* gate_W  = (const float*)d_in[17];
    const float* gate_U  = (const float*)d_in[18];
    const float* FC1     = (const float*)d_in[19];
    const float* FC2     = (const float*)d_in[20];
    const float* Wlin    = (const float*)d_in[21];
    const float* blin    = (const float*)d_in[22];
    float* out = (float*)d_out;

    float* X    = pool + OFF_X;
    float* PF   = pool + OFF_P0F;
    float* PB   = pool + OFF_P0B;
    float* O0   = pool + OFF_O0;
    float* HSA  = pool + OFF_HSA;
    float* HSB  = pool + OFF_HSB;
    float* C4   = pool + OFF_C4;
    float* HS1  = pool + OFF_HS1;
    float* HS2  = pool + OFF_HS2;
    float* Z    = pool + OFF_Z;
    float* HC3  = pool + OFF_HC3;
    float* WHHR  = pool + OFF_WHHR;   // 4 x [1200][300]: l0f,l0b,l1f,l1b
    float* WIHR0 = pool + OFF_WIHR0;  // 2 x [1200][300]
    float* WIHR1 = pool + OFF_WIHR1;  // 2 x [1200][600]
    float* BR    = pool + OFF_BR;     // 4 x [1200]
    float* BATT = pool + OFF_BATT;
    float* EA   = pool + OFF_EA;

    const int LN = L_SEQ * N_NODES;   // 17300
    const size_t W3 = (size_t)G4 * 300, W6 = (size_t)G4 * 600;

    // ---- weight reorders (gate-interleaved rows) ----
    {
        int thr = 256;
        int g3 = (int)((W3 + thr - 1) / thr), g6 = (int)((W6 + thr - 1) / thr);
        int g1 = (G4 + thr - 1) / thr;
        reorder_rows_kernel<<<g3, thr>>>(Whh_l0f, WHHR + 0 * W3, 300);
        reorder_rows_kernel<<<g3, thr>>>(Whh_l0b, WHHR + 1 * W3, 300);
        reorder_rows_kernel<<<g3, thr>>>(Whh_l1f, WHHR + 2 * W3, 300);
        reorder_rows_kernel<<<g3, thr>>>(Whh_l1b, WHHR + 3 * W3, 300);
        reorder_rows_kernel<<<g3, thr>>>(Wih_l0f, WIHR0 + 0 * W3, 300);
        reorder_rows_kernel<<<g3, thr>>>(Wih_l0b, WIHR0 + 1 * W3, 300);
        reorder_rows_kernel<<<g6, thr>>>(Wih_l1f, WIHR1 + 0 * W6, 600);
        reorder_rows_kernel<<<g6, thr>>>(Wih_l1b, WIHR1 + 1 * W6, 600);
        reorder_rows_kernel<<<g1, thr>>>(b_l0f, BR + 0 * G4, 1);
        reorder_rows_kernel<<<g1, thr>>>(b_l0b, BR + 1 * G4, 1);
        reorder_rows_kernel<<<g1, thr>>>(b_l1f, BR + 2 * G4, 1);
        reorder_rows_kernel<<<g1, thr>>>(b_l1b, BR + 3 * G4, 1);
    }

    // ---- init states ----
    memzero_kernel<<<((int)SZ_NG4 + 255) / 256, 256>>>(HSA, (int)SZ_NG4);
    memzero_kernel<<<(4 * (int)SZ_NH + 255) / 256, 256>>>(C4, 4 * (int)SZ_NH);

    // ---- embedding ----
    embed_kernel<<<(int)((SZ_X + 255) / 256), 256>>>(tokens, emb, X);

    // ---- layer-0 input projections (reordered layout) ----
    gemm128_kernel<1, 0><<<grid128(LN, G4), 256>>>(
        LN, G4, D_EMB, X, D_EMB, WIHR0 + 0 * W3, 300, BR + 0 * G4, 0, PF, G4);
    gemm128_kernel<1, 0><<<grid128(LN, G4), 256>>>(
        LN, G4, D_EMB, X, D_EMB, WIHR0 + 1 * W3, 300, BR + 1 * G4, 0, PB, G4);

    // ---- layer-0 scan (fused GEMM+cell, h double-buffered) ----
    {
        dim3 grid = grid64(N_NODES, G4); grid.z = 2;
        const float* hin = HSA; float* hout = HSB;
        for (int t = 0; t < L_SEQ; t++) {
            lstm_fused_kernel<<<grid, 256>>>(
                hin, hout, 0, 300,
                WHHR + 0 * W3, WHHR + 1 * W3,
                PF + (size_t)t * N_NODES * G4,
                PB + (size_t)(L_SEQ - 1 - t) * N_NODES * G4,
                C4, O0, t);
            const float* tmp = hin; hin = hout; hout = (float*)tmp;
        }
    }

    // ---- layer-1 input projections ----
    gemm128_kernel<1, 0><<<grid128(LN, G4), 256>>>(
        LN, G4, 600, O0, 600, WIHR1 + 0 * W6, 600, BR + 2 * G4, 0, PF, G4);
    gemm128_kernel<1, 0><<<grid128(LN, G4), 256>>>(
        LN, G4, 600, O0, 600, WIHR1 + 1 * W6, 600, BR + 3 * G4, 0, PB, G4);

    // ---- layer-1 scan (cols 600/900, c slices 2,3) ----
    {
        dim3 grid = grid64(N_NODES, G4); grid.z = 2;
        const float* hin = HSA; float* hout = HSB;
        for (int t = 0; t < L_SEQ; t++) {
            lstm_fused_kernel<<<grid, 256>>>(
                hin, hout, 600, 900,
                WHHR + 2 * W3, WHHR + 3 * W3,
                PF + (size_t)t * N_NODES * G4,
                PB + (size_t)(L_SEQ - 1 - t) * N_NODES * G4,
                C4 + 2 * SZ_NH, nullptr, t);
            const float* tmp = hin; hin = hout; hout = (float*)tmp;
        }
    }
    // L_SEQ=50 (even): final h for both layers lands in HSA.

    // ---- two gate+GAT stages ----
    run_gate_gat(HSA, HS1, gate_W, gate_U, W_gat, a_gat, adj, pool);
    run_gate_gat(HS1, HS2, gate_W, gate_U, W_gat, a_gat, adj, pool);

    // ---- final head ----
    zassemble_kernel<<<(N_NODES * G4 + 255) / 256, 256>>>(HS2, Z);
    gemm128_kernel<0, 1><<<grid128(N_NODES, 9600), 256>>>(
        N_NODES, 9600, 4800, Z, 4800, FC1, 9600, nullptr, 0, HC3, 9600);
    rows_dot_kernel<1><<<N_NODES, 256>>>(HC3, 9600, FC2, 9600, BATT);
    colsum_kernel<<<(G4 + 255) / 256, 256>>>(HS2, G4, N_NODES, nullptr,
                                             1.0f / (float)N_NODES, EA, G4);
    colsum_kernel<<<(G4 + 255) / 256, 256>>>(HS2, G4, N_NODES, BATT, 1.0f, EA + G4, G4);
    final_kernel<<<1, 256>>>(EA, Wlin, blin, out);
}